// round 16
// baseline (speedup 1.0000x reference)
#include <cuda_runtime.h>
#include <cuda_fp16.h>
#include <cstdint>

// Problem constants
#define MDIM 16384          // B*L
#define NDIM 1024
#define KDIM 1024
#define LSEQ 2048
#define NHEADS 8
#define PDIM 128
#define RAD 7

// GEMM tiling: CTA 128x128, 4 warps (2x2), warp tile 64x64, KC=64
#define BT 128
#define KC 64               // k-chunk in fp16 elems (128B per row)
#define NKCH (KDIM / KC)    // 16
#define ROWB 144            // 128B data + 16B pad (stride 36 words: conflict-free)
#define TILE_B (BT * ROWB)  // 18432 B per operand tile
#define A_O 0
#define B_O TILE_B
#define STAGE_B (2 * TILE_B)          // 36864
#define NSTAGE 3
#define SMEM_TOTAL (NSTAGE * STAGE_B) // 110592 (x2 CTAs = 216KB/SM <= 228KB)

// ---------------- device scratch (no allocs allowed) ----------------
__device__ __half g_vh [(size_t)MDIM * NDIM];   // v in fp16
__device__ __half g_xh [(size_t)MDIM * KDIM];
__device__ __half g_ah [(size_t)MDIM * KDIM];
__device__ __half g_wih[(size_t)NDIM * KDIM];
__device__ __half g_woh[(size_t)NDIM * KDIM];

// ---------------- helpers ----------------
__device__ __forceinline__ uint32_t smem_u32(const void* p) {
    uint32_t a;
    asm("{ .reg .u64 t; cvta.to.shared.u64 t, %1; cvt.u32.u64 %0, t; }" : "=r"(a) : "l"(p));
    return a;
}
__device__ __forceinline__ void cp16(uint32_t dst, const void* src) {
    asm volatile("cp.async.cg.shared.global [%0], [%1], 16;" :: "r"(dst), "l"(src));
}
__device__ __forceinline__ void ldmx4(uint32_t* r, uint32_t addr) {
    asm volatile("ldmatrix.sync.aligned.m8n8.x4.shared.b16 {%0,%1,%2,%3}, [%4];"
                 : "=r"(r[0]), "=r"(r[1]), "=r"(r[2]), "=r"(r[3]) : "r"(addr));
}
__device__ __forceinline__ void mma16816(float* c, const uint32_t* a, const uint32_t* b) {
    asm volatile(
        "mma.sync.aligned.m16n8k16.row.col.f32.f16.f16.f32 "
        "{%0,%1,%2,%3}, {%4,%5,%6,%7}, {%8,%9}, {%0,%1,%2,%3};"
        : "+f"(c[0]), "+f"(c[1]), "+f"(c[2]), "+f"(c[3])
        : "r"(a[0]), "r"(a[1]), "r"(a[2]), "r"(a[3]), "r"(b[0]), "r"(b[1]));
}

// ---------------- single-pass fp16 GEMM, 64x64 warp tile, KC=64 ---------------
// C[m,n] = sum_k Ah[m,k] * Bh[n,k]  (fp32 accumulate)
template <typename OT>
__global__ void __launch_bounds__(128, 2)
gemm_f16(const __half* __restrict__ ah, const __half* __restrict__ bh,
         OT* __restrict__ C)
{
    extern __shared__ char smem[];
    const uint32_t sb = smem_u32(smem);
    const int tid = threadIdx.x;
    const int wid = tid >> 5, lane = tid & 31;
    const int mBase = blockIdx.y * BT, nBase = blockIdx.x * BT;
    const int warpM = wid & 1;        // 0..1 -> 64-row slab
    const int warpN = wid >> 1;       // 0..1 -> 64-col slab

    float acc[4][8][4];               // 64x64 per warp = 128 regs
#pragma unroll
    for (int i = 0; i < 4; i++)
#pragma unroll
        for (int j = 0; j < 8; j++)
#pragma unroll
            for (int k = 0; k < 4; k++) acc[i][j][k] = 0.f;

    // ldmatrix base addresses (stage-relative, ko added per k-step)
    const uint32_t a_addr = (uint32_t)((warpM * 64 + (lane & 15)) * ROWB + ((lane >> 4) * 16));
    const uint32_t b_row  = (uint32_t)(warpN * 64 + (lane & 7) + ((lane >> 4) << 3));
    const uint32_t b_addr = b_row * ROWB + (((lane >> 3) & 1) * 16);

    // global->smem: thread owns row tid; 8x16B segments per array
    auto load_chunk = [&](uint32_t stage, int k0) {
        const char* pa = (const char*)(ah + (size_t)(mBase + tid) * KDIM + k0);
        const char* pb = (const char*)(bh + (size_t)(nBase + tid) * KDIM + k0);
        const uint32_t sd = (uint32_t)tid * ROWB;
#pragma unroll
        for (int s = 0; s < 8; s++) {
            cp16(stage + A_O + sd + s * 16, pa + s * 16);
            cp16(stage + B_O + sd + s * 16, pb + s * 16);
        }
        asm volatile("cp.async.commit_group;" ::: "memory");
    };

    // 3-stage pipeline prologue: chunks 0,1 in flight
    load_chunk(sb + 0 * STAGE_B, 0);
    load_chunk(sb + 1 * STAGE_B, KC);

    uint32_t af[2][4][4], bf[2][4][4];    // double-buffered fragments

    for (int ch = 0; ch < NKCH; ch++) {
        const uint32_t cur = sb + (uint32_t)(ch % NSTAGE) * STAGE_B;
        asm volatile("cp.async.wait_group 1;" ::: "memory");  // chunk ch resident
        __syncthreads();
        if (ch + 2 < NKCH)
            load_chunk(sb + (uint32_t)((ch + 2) % NSTAGE) * STAGE_B, (ch + 2) * KC);
        else
            asm volatile("cp.async.commit_group;" ::: "memory");  // keep group invariant

        // fragment pipeline across the 4 k16 steps of this chunk
#pragma unroll
        for (int mf = 0; mf < 4; mf++)
            ldmx4(af[0][mf], cur + A_O + a_addr + mf * 16 * ROWB);
#pragma unroll
        for (int nf2 = 0; nf2 < 4; nf2++)
            ldmx4(bf[0][nf2], cur + B_O + b_addr + nf2 * 16 * ROWB);

#pragma unroll
        for (int kk = 0; kk < 4; kk++) {
            const int bufc = kk & 1, bufn = bufc ^ 1;
            if (kk < 3) {
                const uint32_t ko = (uint32_t)(kk + 1) * 32;
#pragma unroll
                for (int mf = 0; mf < 4; mf++)
                    ldmx4(af[bufn][mf], cur + A_O + a_addr + mf * 16 * ROWB + ko);
#pragma unroll
                for (int nf2 = 0; nf2 < 4; nf2++)
                    ldmx4(bf[bufn][nf2], cur + B_O + b_addr + nf2 * 16 * ROWB + ko);
            }
#pragma unroll
            for (int mf = 0; mf < 4; mf++)
#pragma unroll
                for (int nf = 0; nf < 8; nf++)
                    mma16816(acc[mf][nf], af[bufc][mf], &bf[bufc][nf >> 1][(nf & 1) * 2]);
        }
    }

    // epilogue
    const int r0 = mBase + warpM * 64 + (lane >> 2);
    const int c0 = nBase + warpN * 64 + (lane & 3) * 2;
#pragma unroll
    for (int mf = 0; mf < 4; mf++)
#pragma unroll
        for (int nf = 0; nf < 8; nf++) {
            if constexpr (sizeof(OT) == 4) {
                float* p = (float*)C + (size_t)(r0 + mf * 16) * NDIM + c0 + nf * 8;
                *(float2*)p                      = make_float2(acc[mf][nf][0], acc[mf][nf][1]);
                *(float2*)(p + (size_t)8 * NDIM) = make_float2(acc[mf][nf][2], acc[mf][nf][3]);
            } else {
                __half* p = (__half*)C + (size_t)(r0 + mf * 16) * NDIM + c0 + nf * 8;
                *(__half2*)p                      = __floats2half2_rn(acc[mf][nf][0], acc[mf][nf][1]);
                *(__half2*)(p + (size_t)8 * NDIM) = __floats2half2_rn(acc[mf][nf][2], acc[mf][nf][3]);
            }
        }
}

// ---------------- fused fp32 -> fp16 prep (x, W_in, W_out in one launch) ------
__device__ __forceinline__ uint32_t pack_h2(__half a, __half b) {
    return (uint32_t)__half_as_ushort(a) | ((uint32_t)__half_as_ushort(b) << 16);
}
__device__ __forceinline__ void cvt4(const float* in, __half* out, int i) {
    float4 v = ((const float4*)in)[i];
    ((uint2*)out)[i] = make_uint2(
        pack_h2(__float2half_rn(v.x), __float2half_rn(v.y)),
        pack_h2(__float2half_rn(v.z), __float2half_rn(v.w)));
}

#define NX4 (MDIM * KDIM / 4)
#define NW4 (NDIM * KDIM / 4)

__global__ void prep_f16(const float* __restrict__ x, const float* __restrict__ wi,
                         const float* __restrict__ wo,
                         __half* __restrict__ xh, __half* __restrict__ wih,
                         __half* __restrict__ woh)
{
    int i = blockIdx.x * blockDim.x + threadIdx.x;
    if (i < NX4)                 cvt4(x,  xh,  i);
    else if (i < NX4 + NW4)      cvt4(wi, wih, i - NX4);
    else if (i < NX4 + 2 * NW4)  cvt4(wo, woh, i - NX4 - NW4);
}

// ---------------- analytic Gaussian attention = fixed 15-tap conv -------------
__device__ __forceinline__ float gw(int d) {
    int a = d < 0 ? -d : d;
    switch (a) {
        case 0: return 1.0f;
        case 1: return 0.60653065971e0f;
        case 2: return 0.13533528324e0f;
        case 3: return 1.11089965382e-2f;
        case 4: return 3.35462627903e-4f;
        case 5: return 3.72665317208e-6f;
        case 6: return 1.52299797447e-8f;
        default: return 2.28973484867e-11f;
    }
}

// v (fp16) -> attended (fp16); fp32 accumulation of the 15 taps.
__global__ void conv_attn_f16(const __half* __restrict__ v, __half* __restrict__ att)
{
    const int h  = blockIdx.y;
    const int b  = blockIdx.z;
    const int q  = blockIdx.x * blockDim.y + threadIdx.y;
    const int p4 = threadIdx.x;              // 0..31, 4 halves each

    int c;
    switch (h) {
        case 0: case 5: c = q;        break;
        case 1: case 6: c = q - 1;    break;
        case 2: case 7: c = q + 1;    break;
        case 3:         c = 0;        break;
        default:        c = LSEQ - 1; break;
    }

    float Z = 0.0f;
#pragma unroll
    for (int d = -RAD; d <= RAD; d++) {
        int k = c + d;
        if (k >= 0 && k < LSEQ) Z += gw(d);
    }
    const float invZ = 1.0f / Z;

    const __half* base = v + (size_t)b * LSEQ * NDIM + h * PDIM + p4 * 4;
    float a0 = 0.f, a1 = 0.f, a2 = 0.f, a3 = 0.f;
#pragma unroll
    for (int d = -RAD; d <= RAD; d++) {
        int k = c + d;
        if (k >= 0 && k < LSEQ) {
            float w = gw(d) * invZ;
            uint2 raw = *(const uint2*)(base + (size_t)k * NDIM);
            __half2 v01 = *(__half2*)&raw.x;
            __half2 v23 = *(__half2*)&raw.y;
            float2 f01 = __half22float2(v01);
            float2 f23 = __half22float2(v23);
            a0 = fmaf(w, f01.x, a0);
            a1 = fmaf(w, f01.y, a1);
            a2 = fmaf(w, f23.x, a2);
            a3 = fmaf(w, f23.y, a3);
        }
    }
    size_t oi = (((size_t)b * LSEQ + q) * NDIM + h * PDIM + p4 * 4) / 4; // uint2 idx
    __half2 o01 = __floats2half2_rn(a0, a1);
    __half2 o23 = __floats2half2_rn(a2, a3);
    ((uint2*)att)[oi] = make_uint2(*(uint32_t*)&o01, *(uint32_t*)&o23);
}

// ---------------- launcher ----------------
extern "C" void kernel_launch(void* const* d_in, const int* in_sizes, int n_in,
                              void* d_out, int out_size)
{
    const float* x     = (const float*)d_in[0];
    const float* W_in  = (const float*)d_in[1];
    const float* W_out = (const float*)d_in[2];
    float* out = (float*)d_out;

    __half *vh,*xh,*ah,*wih,*woh;
    cudaGetSymbolAddress((void**)&vh,  g_vh);
    cudaGetSymbolAddress((void**)&xh,  g_xh);
    cudaGetSymbolAddress((void**)&ah,  g_ah);
    cudaGetSymbolAddress((void**)&wih, g_wih);
    cudaGetSymbolAddress((void**)&woh, g_woh);

    cudaFuncSetAttribute(gemm_f16<__half>, cudaFuncAttributeMaxDynamicSharedMemorySize, SMEM_TOTAL);
    cudaFuncSetAttribute(gemm_f16<float>,  cudaFuncAttributeMaxDynamicSharedMemorySize, SMEM_TOTAL);

    const int ntot = NX4 + 2 * NW4;
    prep_f16<<<(ntot + 255) / 256, 256>>>(x, W_in, W_out, xh, wih, woh);

    dim3 ggrid(NDIM / BT, MDIM / BT);   // (8, 128)
    gemm_f16<__half><<<ggrid, 128, SMEM_TOTAL>>>(xh, wih, vh);

    conv_attn_f16<<<dim3(LSEQ / 8, NHEADS, 8), dim3(32, 8)>>>(vh, ah);

    gemm_f16<float><<<ggrid, 128, SMEM_TOTAL>>>(ah, woh, out);
}